// round 16
// baseline (speedup 1.0000x reference)
#include <cuda_runtime.h>
#include <cuda_fp16.h>
#include <math.h>
#include <stdint.h>

#define EPSF 1e-6f
#define NINPUT 64
#define NLAYER 63

// ---------------------------------------------------------------------------
// Persistent scratch (no allocations allowed)
// ---------------------------------------------------------------------------
__device__ __align__(16) float g_lc[512];     // per-layer F constants (63*8 used)
__device__ __align__(16) uint2 g_Pf[1024];    // fp16 P in m16n8k16 B-fragment order

// Layer constants in the constant bank (c-bank operands, zero LSU traffic)
__constant__ float4 c_lc[NLAYER * 2];

// ---------------------------------------------------------------------------
// helpers
// ---------------------------------------------------------------------------
__device__ __forceinline__ float ex2(float t) {
    float r; asm("ex2.approx.ftz.f32 %0, %1;" : "=f"(r) : "f"(t)); return r;
}
__device__ __forceinline__ float lg2(float t) {
    float r; asm("lg2.approx.ftz.f32 %0, %1;" : "=f"(r) : "f"(t)); return r;
}
__device__ __forceinline__ float rcpf(float t) {
    float r; asm("rcp.approx.ftz.f32 %0, %1;" : "=f"(r) : "f"(t)); return r;
}
__device__ __forceinline__ uint32_t f16x2_rn(float lo, float hi) {
    __half2 h = __floats2half2_rn(lo, hi);
    return *reinterpret_cast<uint32_t*>(&h);
}
__device__ __forceinline__ uint32_t ldpack(const float* p) {   // 2 f32 -> f16x2
    float2 f = *reinterpret_cast<const float2*>(p);
    return f16x2_rn(f.x, f.y);
}
__device__ __forceinline__ void mma_fp16(float* d, const uint32_t* a, uint32_t b0,
                                         uint32_t b1) {
    asm("mma.sync.aligned.m16n8k16.row.col.f32.f16.f16.f32 "
        "{%0,%1,%2,%3}, {%4,%5,%6,%7}, {%8,%9}, {%0,%1,%2,%3};"
        : "+f"(d[0]), "+f"(d[1]), "+f"(d[2]), "+f"(d[3])
        : "r"(a[0]), "r"(a[1]), "r"(a[2]), "r"(a[3]), "r"(b0), "r"(b1));
}

// 8-partial dot of two 64-float rows (both float4-aligned in SMEM)
__device__ __forceinline__ float dot64_ilp8(const float4* a, const float4* b) {
    float s0 = 0.f, s1 = 0.f, s2 = 0.f, s3 = 0.f;
    float s4 = 0.f, s5 = 0.f, s6 = 0.f, s7 = 0.f;
    #pragma unroll
    for (int q = 0; q < 16; q += 2) {
        float4 a0 = a[q], b0 = b[q], a1 = a[q + 1], b1 = b[q + 1];
        s0 = fmaf(a0.x, b0.x, s0); s1 = fmaf(a0.y, b0.y, s1);
        s2 = fmaf(a0.z, b0.z, s2); s3 = fmaf(a0.w, b0.w, s3);
        s4 = fmaf(a1.x, b1.x, s4); s5 = fmaf(a1.y, b1.y, s5);
        s6 = fmaf(a1.z, b1.z, s6); s7 = fmaf(a1.w, b1.w, s7);
    }
    return ((s0 + s1) + (s2 + s3)) + ((s4 + s5) + (s6 + s7));
}

// ---------------------------------------------------------------------------
// Setup: u/v-form Sinkhorn, 8-partial ILP dots on M and Mt (both row-major)
// ---------------------------------------------------------------------------
__global__ __launch_bounds__(256) void setup_kernel(const float* __restrict__ logits,
                                                    const float* __restrict__ weights,
                                                    const float* __restrict__ biases)
{
    __shared__ __align__(16) float M[64 * 68];
    __shared__ __align__(16) float Mt[64 * 68];
    __shared__ __align__(16) float u[64], v[64];
    const int tid = threadIdx.x;

    for (int i = tid; i < 4096; i += 256) {
        int r = i >> 6, c = i & 63;
        float m = __expf(logits[i]);
        M[r * 68 + c]  = m;
        Mt[c * 68 + r] = m;
    }
    if (tid < 64) v[tid] = 1.0f;
    __syncthreads();

    for (int it = 0; it < 20; ++it) {
        if (tid < 64)
            u[tid] = rcpf(dot64_ilp8(reinterpret_cast<const float4*>(&M[tid * 68]),
                                     reinterpret_cast<const float4*>(v)));
        __syncthreads();
        if (tid < 64)
            v[tid] = rcpf(dot64_ilp8(reinterpret_cast<const float4*>(&Mt[tid * 68]),
                                     reinterpret_cast<const float4*>(u)));
        __syncthreads();
    }

    // m16n8k16 B-fragment order (R9-verified):
    //   g_Pf[(kt*8+nt)*32 + lane] = { f16x2(P[16kt+2tg][8nt+g], P[16kt+2tg+1][8nt+g]),
    //                                 f16x2(P[16kt+2tg+8][8nt+g], P[16kt+2tg+9][8nt+g]) }
    for (int i = tid; i < 1024; i += 256) {
        int lane = i & 31, ntk = i >> 5;
        int nt = ntk & 7, kt = ntk >> 3;
        int g = lane >> 2, tg = lane & 3;
        int k0 = kt * 16 + 2 * tg, n = nt * 8 + g;
        float p0 = u[k0]     * M[k0 * 68 + n]       * v[n];
        float p1 = u[k0 + 1] * M[(k0 + 1) * 68 + n] * v[n];
        float p8 = u[k0 + 8] * M[(k0 + 8) * 68 + n] * v[n];
        float p9 = u[k0 + 9] * M[(k0 + 9) * 68 + n] * v[n];
        g_Pf[i] = make_uint2(f16x2_rn(p0, p1), f16x2_rn(p8, p9));
    }

    // Per-layer constants: r = A + bw0*xc + bw1*yc + C * exp2(e0*log2(xs)+e1*log2(ys))
    if (tid < NLAYER) {
        float w0 = weights[tid], w1 = 1.0f - w0, a = biases[tid];
        float A, C, cl, e0 = 0.0f, e1 = 0.0f, off;
        if (fabsf(a - 0.5f) < EPSF) {
            A = 0.0f; cl = 1.0f; C = 0.0f; off = 0.0f;
        } else if (a < 0.5f) {
            float ar = fminf(fmaxf(1.0f - a, -1.0f + EPSF), 2.0f - EPSF);
            float p  = sqrtf(3.0f / fmaxf(2.0f - ar, EPSF)) - 1.0f;
            e0 = 2.0f * w0 * p; e1 = 2.0f * w1 * p;
            float bl, bg;
            if      (fabsf(ar - 2.0f) < EPSF) { bl = 0.0f; bg = 0.0f; }
            else if (ar >= 0.75f)             { bl = 0.0f; bg = 1.0f; }
            else if (ar > 0.5f)               { bl = 3.0f - 4.0f * ar; bg = 4.0f * ar - 2.0f; }
            else                              { bl = 1.0f; bg = 0.0f; }
            A = 1.0f - bl; cl = bl; C = -bg; off = 1.0f;
        } else {
            float p = sqrtf(3.0f / fmaxf(2.0f - a, EPSF)) - 1.0f;
            e0 = 2.0f * w0 * p; e1 = 2.0f * w1 * p;
            float bl, bg;
            if      (fabsf(a - 2.0f) < EPSF) { bl = 0.0f; bg = 0.0f; }
            else if (a >= 0.75f)             { bl = 0.0f; bg = 1.0f; }
            else if (a > 0.5f)               { bl = 3.0f - 4.0f * a; bg = 4.0f * a - 2.0f; }
            else                             { bl = 1.0f; bg = 0.0f; }
            A = 0.0f; cl = bl; C = bg; off = 0.0f;
        }
        float* lc = &g_lc[tid * 8];
        lc[0] = cl * w0; lc[1] = cl * w1; lc[2] = A;   lc[3] = C;
        lc[4] = e0;      lc[5] = e1;      lc[6] = off; lc[7] = a;
    }
}

// ---------------------------------------------------------------------------
// Main: PERSISTENT warps, TRIPLE-buffer / triple-tile iterations, scan ILP-3.
// 296 CTAs x 128 thr (4 warps), 3 private buffers per warp (XW=72, 9216 B):
// SMEM 110592 B -> 2 CTAs/SM = 8 warps/SM. Per-warp scan MUFU demand is
// 72 cyc per ~52-cyc chain (138%) -> throughput-bound within a single warp,
// immune to cross-warp phase convoys. Layer consts from c-bank.
// ---------------------------------------------------------------------------
#define XW 72
#define XBUF_W 2304                       // 32*72 words = 9216 B
#define LS 34
#define NBUF 3
#define WSLICE_W (NBUF * XBUF_W)
#define SM_SIZE (4 * NBUF * 9216)         // 110592 B -> 2 CTAs/SM
#define NCTAS 296

__global__ __launch_bounds__(128, 2) void main_kernel(const float* __restrict__ x,
                                                      float* __restrict__ out,
                                                      int batch)
{
    extern __shared__ __align__(16) uint8_t smem[];
    const int tid = threadIdx.x, w = tid >> 5, lane = tid & 31;
    const int g = lane >> 2, tg = lane & 3;

    float* Wbase = reinterpret_cast<float*>(smem) + w * WSLICE_W;
    uint32_t sbase;
    asm("{ .reg .u64 t; cvta.to.shared.u64 t, %1; cvt.u32.u64 %0, t; }"
        : "=r"(sbase) : "l"(Wbase));

    const int ntiles = (batch + 31) >> 5;
    const int warpId = blockIdx.x * 4 + w;
    const int wstride = gridDim.x * 4;
    const size_t f4_limit = (size_t)batch * 16;
    const float4* gx = reinterpret_cast<const float4*>(x);

    auto issue = [&](int tile, int p) {
        if (tile < ntiles) {
            uint32_t dstb = sbase + p * 9216;
            #pragma unroll
            for (int t = 0; t < 16; ++t) {
                int i = lane + t * 32;
                size_t gi = (size_t)tile * 512 + i;
                if (gi < f4_limit) {
                    int r = i >> 4, c4 = i & 15;
                    uint32_t d = dstb + (uint32_t)(r * XW + c4 * 4) * 4;
                    asm volatile("cp.async.cg.shared.global [%0], [%1], 16;"
                                 :: "r"(d), "l"(gx + gi) : "memory");
                }
            }
        }
        asm volatile("cp.async.commit_group;" ::: "memory");
    };

    auto gemm = [&](const float* Xb, float (*d)[8][4]) {
        #pragma unroll
        for (int mt = 0; mt < 2; ++mt)
            #pragma unroll
            for (int nt = 0; nt < 8; ++nt)
                #pragma unroll
                for (int e = 0; e < 4; ++e) d[mt][nt][e] = 0.0f;
        #pragma unroll
        for (int kt = 0; kt < 4; ++kt) {
            const int kc = kt * 16 + 2 * tg;
            uint32_t a[2][4];
            #pragma unroll
            for (int mt = 0; mt < 2; ++mt) {
                int r0 = g + mt * 16;
                a[mt][0] = ldpack(&Xb[r0 * XW + kc]);
                a[mt][1] = ldpack(&Xb[(r0 + 8) * XW + kc]);
                a[mt][2] = ldpack(&Xb[r0 * XW + kc + 8]);
                a[mt][3] = ldpack(&Xb[(r0 + 8) * XW + kc + 8]);
            }
            #pragma unroll
            for (int nt = 0; nt < 8; ++nt) {
                uint2 b = __ldg(&g_Pf[(kt * 8 + nt) * 32 + lane]);
                mma_fp16(d[0][nt], a[0], b.x, b.y);
                mma_fp16(d[1][nt], a[1], b.x, b.y);
            }
        }
    };

    auto epilogue = [&](float* SLb, float (*d)[8][4]) {
        #pragma unroll
        for (int mt = 0; mt < 2; ++mt) {
            int r0 = mt * 16 + g;
            #pragma unroll
            for (int nt = 0; nt < 8; ++nt) {
                int c0 = nt * 8 + tg * 2;
                SLb[c0 * LS + r0]           = d[mt][nt][0];
                SLb[(c0 + 1) * LS + r0]     = d[mt][nt][1];
                SLb[c0 * LS + r0 + 8]       = d[mt][nt][2];
                SLb[(c0 + 1) * LS + r0 + 8] = d[mt][nt][3];
            }
        }
    };

    issue(warpId, 0);
    issue(warpId + wstride, 1);
    issue(warpId + 2 * wstride, 2);

    float* buf[NBUF] = { Wbase, Wbase + XBUF_W, Wbase + 2 * XBUF_W };

    for (int t0 = warpId; t0 < ntiles; t0 += 3 * wstride) {
        const int t1 = t0 + wstride;
        const int t2 = t0 + 2 * wstride;
        float d[2][8][4];

        asm volatile("cp.async.wait_group 2;" ::: "memory");
        __syncwarp();
        gemm(buf[0], d);
        __syncwarp();
        epilogue(buf[0], d);

        asm volatile("cp.async.wait_group 1;" ::: "memory");
        __syncwarp();
        gemm(buf[1], d);
        __syncwarp();
        epilogue(buf[1], d);

        asm volatile("cp.async.wait_group 0;" ::: "memory");
        __syncwarp();
        gemm(buf[2], d);
        __syncwarp();
        epilogue(buf[2], d);
        __syncwarp();

        // ---- triple scan (ILP-3), consts from c-bank ----
        float s[NBUF];
        #pragma unroll
        for (int q = 0; q < NBUF; ++q) s[q] = buf[q][lane];

        #pragma unroll
        for (int i = 0; i < NLAYER; ++i) {
            float4 k0 = c_lc[i * 2];
            float4 k1 = c_lc[i * 2 + 1];
            #pragma unroll
            for (int q = 0; q < NBUF; ++q) {
                float leaf = buf[q][(i + 1) * LS + lane];
                float xc = fminf(fmaxf(s[q],  EPSF), 1.0f - EPSF);
                float yc = fminf(fmaxf(leaf,  EPSF), 1.0f - EPSF);
                float lgx = lg2(fabsf(k1.z - xc));
                float lgy = lg2(fabsf(k1.z - yc));
                float t  = fmaf(k1.x, lgx, k1.y * lgy);
                float gg = ex2(t);
                s[q] = fmaf(k0.w, gg, fmaf(k0.y, yc, fmaf(k0.x, xc, k0.z)));
            }
        }

        int r0 = t0 * 32 + lane;
        if (r0 < batch) out[r0] = s[0];
        if (t1 < ntiles) {
            int r1 = t1 * 32 + lane;
            if (r1 < batch) out[r1] = s[1];
        }
        if (t2 < ntiles) {
            int r2 = t2 * 32 + lane;
            if (r2 < batch) out[r2] = s[2];
        }

        __syncwarp();
        issue(t0 + 3 * wstride, 0);
        issue(t1 + 3 * wstride, 1);
        issue(t2 + 3 * wstride, 2);
    }
}

// ---------------------------------------------------------------------------
// Launch
// ---------------------------------------------------------------------------
extern "C" void kernel_launch(void* const* d_in, const int* in_sizes, int n_in,
                              void* d_out, int out_size)
{
    const float* x       = (const float*)d_in[0];
    const float* logits  = (const float*)d_in[1];
    const float* weights = (const float*)d_in[2];
    const float* biases  = (const float*)d_in[3];
    float* out = (float*)d_out;

    int batch = in_sizes[0] / NINPUT;

    cudaFuncSetAttribute(main_kernel, cudaFuncAttributeMaxDynamicSharedMemorySize, SM_SIZE);

    setup_kernel<<<1, 256>>>(logits, weights, biases);

    // layer consts -> constant bank (D2D async copy; graph-capturable)
    void* lc_dev = nullptr;
    cudaGetSymbolAddress(&lc_dev, g_lc);
    cudaMemcpyToSymbolAsync(c_lc, lc_dev, NLAYER * 8 * sizeof(float), 0,
                            cudaMemcpyDeviceToDevice, 0);

    main_kernel<<<NCTAS, 128, SM_SIZE>>>(x, out, batch);
}

// round 17
// speedup vs baseline: 1.1059x; 1.1059x over previous
#include <cuda_runtime.h>
#include <cuda_fp16.h>
#include <math.h>
#include <stdint.h>

#define EPSF 1e-6f
#define NINPUT 64
#define NLAYER 63

// ---------------------------------------------------------------------------
// Persistent scratch (no allocations allowed)
// ---------------------------------------------------------------------------
__device__ __align__(16) float g_lc[512];     // per-layer F constants (63*8 used)
__device__ __align__(16) uint2 g_Pf[1024];    // fp16 P in m16n8k16 B-fragment order

// Layer constants in the constant bank (c-bank operands, zero LSU traffic)
__constant__ float4 c_lc[NLAYER * 2];

// ---------------------------------------------------------------------------
// helpers
// ---------------------------------------------------------------------------
__device__ __forceinline__ float ex2(float t) {
    float r; asm("ex2.approx.ftz.f32 %0, %1;" : "=f"(r) : "f"(t)); return r;
}
__device__ __forceinline__ float lg2(float t) {
    float r; asm("lg2.approx.ftz.f32 %0, %1;" : "=f"(r) : "f"(t)); return r;
}
__device__ __forceinline__ float rcpf(float t) {
    float r; asm("rcp.approx.ftz.f32 %0, %1;" : "=f"(r) : "f"(t)); return r;
}
__device__ __forceinline__ uint32_t f16x2_rn(float lo, float hi) {
    __half2 h = __floats2half2_rn(lo, hi);
    return *reinterpret_cast<uint32_t*>(&h);
}
__device__ __forceinline__ uint32_t ldpack(const float* p) {   // 2 f32 -> f16x2
    float2 f = *reinterpret_cast<const float2*>(p);
    return f16x2_rn(f.x, f.y);
}
__device__ __forceinline__ void mma_fp16(float* d, const uint32_t* a, uint32_t b0,
                                         uint32_t b1) {
    asm("mma.sync.aligned.m16n8k16.row.col.f32.f16.f16.f32 "
        "{%0,%1,%2,%3}, {%4,%5,%6,%7}, {%8,%9}, {%0,%1,%2,%3};"
        : "+f"(d[0]), "+f"(d[1]), "+f"(d[2]), "+f"(d[3])
        : "r"(a[0]), "r"(a[1]), "r"(a[2]), "r"(a[3]), "r"(b0), "r"(b1));
}

// 8-partial dot of two 64-float rows (both float4-aligned in SMEM)
__device__ __forceinline__ float dot64_ilp8(const float4* a, const float4* b) {
    float s0 = 0.f, s1 = 0.f, s2 = 0.f, s3 = 0.f;
    float s4 = 0.f, s5 = 0.f, s6 = 0.f, s7 = 0.f;
    #pragma unroll
    for (int q = 0; q < 16; q += 2) {
        float4 a0 = a[q], b0 = b[q], a1 = a[q + 1], b1 = b[q + 1];
        s0 = fmaf(a0.x, b0.x, s0); s1 = fmaf(a0.y, b0.y, s1);
        s2 = fmaf(a0.z, b0.z, s2); s3 = fmaf(a0.w, b0.w, s3);
        s4 = fmaf(a1.x, b1.x, s4); s5 = fmaf(a1.y, b1.y, s5);
        s6 = fmaf(a1.z, b1.z, s6); s7 = fmaf(a1.w, b1.w, s7);
    }
    return ((s0 + s1) + (s2 + s3)) + ((s4 + s5) + (s6 + s7));
}

// ---------------------------------------------------------------------------
// Setup: u/v-form Sinkhorn with 8-partial ILP dots on M and Mt
// ---------------------------------------------------------------------------
__global__ __launch_bounds__(256) void setup_kernel(const float* __restrict__ logits,
                                                    const float* __restrict__ weights,
                                                    const float* __restrict__ biases)
{
    __shared__ __align__(16) float M[64 * 68];
    __shared__ __align__(16) float Mt[64 * 68];
    __shared__ __align__(16) float u[64], v[64];
    const int tid = threadIdx.x;

    for (int i = tid; i < 4096; i += 256) {
        int r = i >> 6, c = i & 63;
        float m = __expf(logits[i]);
        M[r * 68 + c]  = m;
        Mt[c * 68 + r] = m;
    }
    if (tid < 64) v[tid] = 1.0f;
    __syncthreads();

    for (int it = 0; it < 20; ++it) {
        if (tid < 64)
            u[tid] = rcpf(dot64_ilp8(reinterpret_cast<const float4*>(&M[tid * 68]),
                                     reinterpret_cast<const float4*>(v)));
        __syncthreads();
        if (tid < 64)
            v[tid] = rcpf(dot64_ilp8(reinterpret_cast<const float4*>(&Mt[tid * 68]),
                                     reinterpret_cast<const float4*>(u)));
        __syncthreads();
    }

    // m16n8k16 B-fragment order (R9-verified):
    //   g_Pf[(kt*8+nt)*32 + lane] = { f16x2(P[16kt+2tg][8nt+g], P[16kt+2tg+1][8nt+g]),
    //                                 f16x2(P[16kt+2tg+8][8nt+g], P[16kt+2tg+9][8nt+g]) }
    for (int i = tid; i < 1024; i += 256) {
        int lane = i & 31, ntk = i >> 5;
        int nt = ntk & 7, kt = ntk >> 3;
        int g = lane >> 2, tg = lane & 3;
        int k0 = kt * 16 + 2 * tg, n = nt * 8 + g;
        float p0 = u[k0]     * M[k0 * 68 + n]       * v[n];
        float p1 = u[k0 + 1] * M[(k0 + 1) * 68 + n] * v[n];
        float p8 = u[k0 + 8] * M[(k0 + 8) * 68 + n] * v[n];
        float p9 = u[k0 + 9] * M[(k0 + 9) * 68 + n] * v[n];
        g_Pf[i] = make_uint2(f16x2_rn(p0, p1), f16x2_rn(p8, p9));
    }

    // Per-layer constants: r = A + bw0*xc + bw1*yc + C * exp2(e0*log2(xs)+e1*log2(ys))
    if (tid < NLAYER) {
        float w0 = weights[tid], w1 = 1.0f - w0, a = biases[tid];
        float A, C, cl, e0 = 0.0f, e1 = 0.0f, off;
        if (fabsf(a - 0.5f) < EPSF) {
            A = 0.0f; cl = 1.0f; C = 0.0f; off = 0.0f;
        } else if (a < 0.5f) {
            float ar = fminf(fmaxf(1.0f - a, -1.0f + EPSF), 2.0f - EPSF);
            float p  = sqrtf(3.0f / fmaxf(2.0f - ar, EPSF)) - 1.0f;
            e0 = 2.0f * w0 * p; e1 = 2.0f * w1 * p;
            float bl, bg;
            if      (fabsf(ar - 2.0f) < EPSF) { bl = 0.0f; bg = 0.0f; }
            else if (ar >= 0.75f)             { bl = 0.0f; bg = 1.0f; }
            else if (ar > 0.5f)               { bl = 3.0f - 4.0f * ar; bg = 4.0f * ar - 2.0f; }
            else                              { bl = 1.0f; bg = 0.0f; }
            A = 1.0f - bl; cl = bl; C = -bg; off = 1.0f;
        } else {
            float p = sqrtf(3.0f / fmaxf(2.0f - a, EPSF)) - 1.0f;
            e0 = 2.0f * w0 * p; e1 = 2.0f * w1 * p;
            float bl, bg;
            if      (fabsf(a - 2.0f) < EPSF) { bl = 0.0f; bg = 0.0f; }
            else if (a >= 0.75f)             { bl = 0.0f; bg = 1.0f; }
            else if (a > 0.5f)               { bl = 3.0f - 4.0f * a; bg = 4.0f * a - 2.0f; }
            else                             { bl = 1.0f; bg = 0.0f; }
            A = 0.0f; cl = bl; C = bg; off = 0.0f;
        }
        float* lc = &g_lc[tid * 8];
        lc[0] = cl * w0; lc[1] = cl * w1; lc[2] = A;   lc[3] = C;
        lc[4] = e0;      lc[5] = e1;      lc[6] = off; lc[7] = a;
    }
}

// ---------------------------------------------------------------------------
// Main (byte-for-byte R12 structure — best measured: 28.9 us):
// PERSISTENT warps, PAIR-tile processing with dual-scan ILP-2.
// 444 CTAs x 128 thr; warp-private 2x9216B buffers; c-bank layer consts.
// ---------------------------------------------------------------------------
#define XW 72
#define XBUF_W 2304                       // 32*72 words = 9216 B
#define LS 34
#define WSLICE_W (2 * XBUF_W)
#define SM_SIZE (4 * 2 * 9216)            // 73728 B per CTA -> 3 CTAs/SM
#define NCTAS 444

__global__ __launch_bounds__(128, 3) void main_kernel(const float* __restrict__ x,
                                                      float* __restrict__ out,
                                                      int batch)
{
    extern __shared__ __align__(16) uint8_t smem[];
    const int tid = threadIdx.x, w = tid >> 5, lane = tid & 31;
    const int g = lane >> 2, tg = lane & 3;

    float* Wbase = reinterpret_cast<float*>(smem) + w * WSLICE_W;
    uint32_t sbase;
    asm("{ .reg .u64 t; cvta.to.shared.u64 t, %1; cvt.u32.u64 %0, t; }"
        : "=r"(sbase) : "l"(Wbase));

    const int ntiles = (batch + 31) >> 5;
    const int warpId = blockIdx.x * 4 + w;
    const int wstride = gridDim.x * 4;
    const size_t f4_limit = (size_t)batch * 16;
    const float4* gx = reinterpret_cast<const float4*>(x);

    auto issue = [&](int tile, int p) {
        if (tile < ntiles) {
            uint32_t dstb = sbase + p * 9216;
            #pragma unroll
            for (int t = 0; t < 16; ++t) {
                int i = lane + t * 32;
                size_t gi = (size_t)tile * 512 + i;
                if (gi < f4_limit) {
                    int r = i >> 4, c4 = i & 15;
                    uint32_t d = dstb + (uint32_t)(r * XW + c4 * 4) * 4;
                    asm volatile("cp.async.cg.shared.global [%0], [%1], 16;"
                                 :: "r"(d), "l"(gx + gi) : "memory");
                }
            }
        }
        asm volatile("cp.async.commit_group;" ::: "memory");
    };

    auto gemm = [&](const float* Xb, float (*d)[8][4]) {
        #pragma unroll
        for (int mt = 0; mt < 2; ++mt)
            #pragma unroll
            for (int nt = 0; nt < 8; ++nt)
                #pragma unroll
                for (int e = 0; e < 4; ++e) d[mt][nt][e] = 0.0f;
        #pragma unroll
        for (int kt = 0; kt < 4; ++kt) {
            const int kc = kt * 16 + 2 * tg;
            uint32_t a[2][4];
            #pragma unroll
            for (int mt = 0; mt < 2; ++mt) {
                int r0 = g + mt * 16;
                a[mt][0] = ldpack(&Xb[r0 * XW + kc]);
                a[mt][1] = ldpack(&Xb[(r0 + 8) * XW + kc]);
                a[mt][2] = ldpack(&Xb[r0 * XW + kc + 8]);
                a[mt][3] = ldpack(&Xb[(r0 + 8) * XW + kc + 8]);
            }
            #pragma unroll
            for (int nt = 0; nt < 8; ++nt) {
                uint2 b = __ldg(&g_Pf[(kt * 8 + nt) * 32 + lane]);
                mma_fp16(d[0][nt], a[0], b.x, b.y);
                mma_fp16(d[1][nt], a[1], b.x, b.y);
            }
        }
    };

    auto epilogue = [&](float* SLb, float (*d)[8][4]) {
        #pragma unroll
        for (int mt = 0; mt < 2; ++mt) {
            int r0 = mt * 16 + g;
            #pragma unroll
            for (int nt = 0; nt < 8; ++nt) {
                int c0 = nt * 8 + tg * 2;
                SLb[c0 * LS + r0]           = d[mt][nt][0];
                SLb[(c0 + 1) * LS + r0]     = d[mt][nt][1];
                SLb[c0 * LS + r0 + 8]       = d[mt][nt][2];
                SLb[(c0 + 1) * LS + r0 + 8] = d[mt][nt][3];
            }
        }
    };

    issue(warpId, 0);
    issue(warpId + wstride, 1);

    float* buf0 = Wbase;
    float* buf1 = Wbase + XBUF_W;

    for (int t0 = warpId; t0 < ntiles; t0 += 2 * wstride) {
        const int t1 = t0 + wstride;
        float d[2][8][4];

        asm volatile("cp.async.wait_group 1;" ::: "memory");
        __syncwarp();
        gemm(buf0, d);
        __syncwarp();
        epilogue(buf0, d);

        asm volatile("cp.async.wait_group 0;" ::: "memory");
        __syncwarp();
        gemm(buf1, d);
        __syncwarp();
        epilogue(buf1, d);
        __syncwarp();

        // ---- dual scan (ILP-2), consts from c-bank ----
        float s0 = buf0[lane];
        float s1 = buf1[lane];
        #pragma unroll
        for (int i = 0; i < NLAYER; ++i) {
            float leaf0 = buf0[(i + 1) * LS + lane];
            float leaf1 = buf1[(i + 1) * LS + lane];
            float4 k0 = c_lc[i * 2];
            float4 k1 = c_lc[i * 2 + 1];

            float xc0 = fminf(fmaxf(s0, EPSF), 1.0f - EPSF);
            float xc1 = fminf(fmaxf(s1, EPSF), 1.0f - EPSF);
            float yc0 = fminf(fmaxf(leaf0, EPSF), 1.0f - EPSF);
            float yc1 = fminf(fmaxf(leaf1, EPSF), 1.0f - EPSF);
            float lgx0 = lg2(fabsf(k1.z - xc0));
            float lgx1 = lg2(fabsf(k1.z - xc1));
            float lgy0 = lg2(fabsf(k1.z - yc0));
            float lgy1 = lg2(fabsf(k1.z - yc1));
            float t0f = fmaf(k1.x, lgx0, k1.y * lgy0);
            float t1f = fmaf(k1.x, lgx1, k1.y * lgy1);
            float gg0 = ex2(t0f);
            float gg1 = ex2(t1f);
            s0 = fmaf(k0.w, gg0, fmaf(k0.y, yc0, fmaf(k0.x, xc0, k0.z)));
            s1 = fmaf(k0.w, gg1, fmaf(k0.y, yc1, fmaf(k0.x, xc1, k0.z)));
        }

        out[t0 * 32 + lane] = s0;
        if (t1 < ntiles) out[t1 * 32 + lane] = s1;

        __syncwarp();
        issue(t0 + 2 * wstride, 0);
        issue(t1 + 2 * wstride, 1);
    }
}

// ---------------------------------------------------------------------------
// Launch
// ---------------------------------------------------------------------------
extern "C" void kernel_launch(void* const* d_in, const int* in_sizes, int n_in,
                              void* d_out, int out_size)
{
    const float* x       = (const float*)d_in[0];
    const float* logits  = (const float*)d_in[1];
    const float* weights = (const float*)d_in[2];
    const float* biases  = (const float*)d_in[3];
    float* out = (float*)d_out;

    int batch = in_sizes[0] / NINPUT;

    cudaFuncSetAttribute(main_kernel, cudaFuncAttributeMaxDynamicSharedMemorySize, SM_SIZE);

    setup_kernel<<<1, 256>>>(logits, weights, biases);

    // layer consts -> constant bank (D2D async copy; graph-capturable)
    void* lc_dev = nullptr;
    cudaGetSymbolAddress(&lc_dev, g_lc);
    cudaMemcpyToSymbolAsync(c_lc, lc_dev, NLAYER * 8 * sizeof(float), 0,
                            cudaMemcpyDeviceToDevice, 0);

    main_kernel<<<NCTAS, 128, SM_SIZE>>>(x, out, batch);
}